// round 13
// baseline (speedup 1.0000x reference)
#include <cuda_runtime.h>

#define LNEPS 1e-3f
#define SCALAR 0.0625f   // 1/sqrt(256)

// ---------------- scratch (device globals; no allocations allowed) ----------
__device__ float g_Fn[2048 * 256];        // LayerNorm(F)
__device__ float g_M [2048 * 256];        // Fn @ W2  (W2 = scalar*Wq@Wk^T)
__device__ float g_W2[256 * 256];
__device__ float g_vsum[2048];            // row sums of V
__device__ float g_sd[64];                // scalar * g_p[d] * w_eff[d]
__device__ float g_sc[2];                 // [0]=sum(g_sd), [1]=scalar*const
__device__ float g_wvsum[256];            // Wv @ ones
__device__ float g_pnum[8][2048];         // split-K softmax partials
__device__ float g_pden[8][2048];

// ---------------- prep A: fold pair-path weights (tiny) ----------------------
__global__ __launch_bounds__(64) void prep_small(
    const float* __restrict__ gp, const float* __restrict__ bp,
    const float* __restrict__ Wpt, const float* __restrict__ bpt,
    const float* __restrict__ Wph)
{
    __shared__ float weff[64];
    int t = threadIdx.x;
    float acc = 0.f;
    #pragma unroll 8
    for (int p = 0; p < 128; ++p) acc += Wpt[t * 128 + p] * Wph[p];
    weff[t] = acc;
    g_sd[t] = SCALAR * gp[t] * acc;
    __syncthreads();
    float v1 = SCALAR * gp[t] * weff[t];
    float v2 = bp[t] * weff[t];
    float v3 = bpt[t] * Wph[t] + bpt[t + 64] * Wph[t + 64];
    #pragma unroll
    for (int o = 16; o; o >>= 1) {
        v1 += __shfl_xor_sync(0xffffffffu, v1, o);
        v2 += __shfl_xor_sync(0xffffffffu, v2, o);
        v3 += __shfl_xor_sync(0xffffffffu, v3, o);
    }
    __shared__ float red[3][2];
    if ((t & 31) == 0) { red[0][t >> 5] = v1; red[1][t >> 5] = v2; red[2][t >> 5] = v3; }
    __syncthreads();
    if (t == 0) {
        g_sc[0] = red[0][0] + red[0][1];
        g_sc[1] = SCALAR * (red[1][0] + red[1][1] + red[2][0] + red[2][1]);
    }
}

// ---------------- prep B: W2 = SCALAR * Wq @ Wk^T (256x256, NT) --------------
// 64 blocks, 32x32 tiles, 2x2 per thread. Row stride 36 floats (144B = 9*16)
// keeps float4 smem accesses 16B-aligned.
__global__ __launch_bounds__(256) void prep_w2(
    const float* __restrict__ Wq, const float* __restrict__ Wk)
{
    __shared__ __align__(16) float As[32][36], Bs[32][36];
    int t = threadIdx.x;
    int m0 = (blockIdx.x >> 3) * 32, n0 = (blockIdx.x & 7) * 32;
    int lr = t >> 3, lc4 = (t & 7) * 4;
    int ty = t >> 4, tx = t & 15;
    float acc[2][2] = {};
    for (int kc = 0; kc < 256; kc += 32) {
        *(float4*)&As[lr][lc4] = *(const float4*)(Wq + (size_t)(m0 + lr) * 256 + kc + lc4);
        *(float4*)&Bs[lr][lc4] = *(const float4*)(Wk + (size_t)(n0 + lr) * 256 + kc + lc4);
        __syncthreads();
        #pragma unroll
        for (int k = 0; k < 32; ++k) {
            float a0 = As[ty * 2][k], a1 = As[ty * 2 + 1][k];
            float b0 = Bs[tx * 2][k], b1 = Bs[tx * 2 + 1][k];
            acc[0][0] += a0 * b0; acc[0][1] += a0 * b1;
            acc[1][0] += a1 * b0; acc[1][1] += a1 * b1;
        }
        __syncthreads();
    }
    #pragma unroll
    for (int i = 0; i < 2; ++i)
        #pragma unroll
        for (int j = 0; j < 2; ++j)
            g_W2[(m0 + ty * 2 + i) * 256 + n0 + tx * 2 + j] = SCALAR * acc[i][j];
}

// ---------------- prep C: wvsum[f] = sum_a Wv[f,a] ---------------------------
__global__ __launch_bounds__(256) void prep_wvsum(const float* __restrict__ Wv)
{
    int warp = threadIdx.x >> 5, lane = threadIdx.x & 31;
    int f = blockIdx.x * 8 + warp;
    const float* row = Wv + (size_t)f * 256;
    float acc = 0.f;
    #pragma unroll
    for (int i = 0; i < 8; ++i) acc += row[lane + 32 * i];
    #pragma unroll
    for (int o = 16; o; o >>= 1) acc += __shfl_xor_sync(0xffffffffu, acc, o);
    if (lane == 0) g_wvsum[f] = acc;
}

// ---------------- LayerNorm(F) + vsum ----------------------------------------
__global__ __launch_bounds__(256) void ln_kernel(
    const float* __restrict__ F, const float* __restrict__ gf,
    const float* __restrict__ bf)
{
    int row  = blockIdx.x * 8 + (threadIdx.x >> 5);
    int lane = threadIdx.x & 31;
    const float* x = F + (size_t)row * 256;
    float4 a = *(const float4*)(x + lane * 4);
    float4 b = *(const float4*)(x + 128 + lane * 4);
    float s = a.x + a.y + a.z + a.w + b.x + b.y + b.z + b.w;
    float q = a.x*a.x + a.y*a.y + a.z*a.z + a.w*a.w
            + b.x*b.x + b.y*b.y + b.z*b.z + b.w*b.w;
    #pragma unroll
    for (int o = 16; o; o >>= 1) {
        s += __shfl_xor_sync(0xffffffffu, s, o);
        q += __shfl_xor_sync(0xffffffffu, q, o);
    }
    float mu   = s * (1.f / 256.f);
    float rinv = rsqrtf(q * (1.f / 256.f) - mu * mu + LNEPS);

    float4 g0 = *(const float4*)(gf + lane * 4);
    float4 b0 = *(const float4*)(bf + lane * 4);
    float4 g1 = *(const float4*)(gf + 128 + lane * 4);
    float4 b1 = *(const float4*)(bf + 128 + lane * 4);
    float4 f0, f1;
    f0.x = (a.x - mu) * rinv * g0.x + b0.x;
    f0.y = (a.y - mu) * rinv * g0.y + b0.y;
    f0.z = (a.z - mu) * rinv * g0.z + b0.z;
    f0.w = (a.w - mu) * rinv * g0.w + b0.w;
    f1.x = (b.x - mu) * rinv * g1.x + b1.x;
    f1.y = (b.y - mu) * rinv * g1.y + b1.y;
    f1.z = (b.z - mu) * rinv * g1.z + b1.z;
    f1.w = (b.w - mu) * rinv * g1.w + b1.w;

    *(float4*)(g_Fn + (size_t)row * 256 + lane * 4)       = f0;
    *(float4*)(g_Fn + (size_t)row * 256 + 128 + lane * 4) = f1;

    float4 w0 = *(const float4*)(g_wvsum + lane * 4);
    float4 w1 = *(const float4*)(g_wvsum + 128 + lane * 4);
    float p = f0.x*w0.x + f0.y*w0.y + f0.z*w0.z + f0.w*w0.w
            + f1.x*w1.x + f1.y*w1.y + f1.z*w1.z + f1.w*w1.w;
    #pragma unroll
    for (int o = 16; o; o >>= 1) p += __shfl_xor_sync(0xffffffffu, p, o);
    if (lane == 0) g_vsum[row] = p;
}

// ---------------- GEMM: M = Fn @ W2  (NN, 128x64 tile, double-buffered) ------
__global__ __launch_bounds__(256) void gemm_M()
{
    __shared__ __align__(16) float As[2][16][132];
    __shared__ __align__(16) float Bs[2][16][68];
    int t  = threadIdx.x;
    int tx = t & 15, ty = t >> 4;
    int m0 = blockIdx.y * 128, n0 = blockIdx.x * 64;

    int arow = t >> 2;
    int ak4  = (t & 3) * 4;
    int bk   = t >> 4;
    int bn4  = (t & 15) * 4;

    const float* Aptr0 = g_Fn + (size_t)(m0 + arow) * 256 + ak4;
    const float* Aptr1 = Aptr0 + 64 * 256;
    const float* Bptr  = g_W2 + (size_t)bk * 256 + n0 + bn4;

    float acc[8][4] = {};
    {
        float4 a0 = *(const float4*)(Aptr0);
        float4 a1 = *(const float4*)(Aptr1);
        float4 bv = *(const float4*)(Bptr);
        As[0][ak4+0][arow] = a0.x; As[0][ak4+1][arow] = a0.y;
        As[0][ak4+2][arow] = a0.z; As[0][ak4+3][arow] = a0.w;
        As[0][ak4+0][arow+64] = a1.x; As[0][ak4+1][arow+64] = a1.y;
        As[0][ak4+2][arow+64] = a1.z; As[0][ak4+3][arow+64] = a1.w;
        *(float4*)&Bs[0][bk][bn4] = bv;
    }
    __syncthreads();
    int cur = 0;
    for (int kt = 0; kt < 16; ++kt) {
        float4 na0, na1, nb;
        if (kt < 15) {
            na0 = *(const float4*)(Aptr0 + (kt + 1) * 16);
            na1 = *(const float4*)(Aptr1 + (kt + 1) * 16);
            nb  = *(const float4*)(Bptr + (size_t)(kt + 1) * 16 * 256);
        }
        #pragma unroll
        for (int k = 0; k < 16; ++k) {
            float4 a0 = *(float4*)&As[cur][k][ty * 8];
            float4 a1 = *(float4*)&As[cur][k][ty * 8 + 4];
            float4 b  = *(float4*)&Bs[cur][k][tx * 4];
            acc[0][0] += a0.x * b.x; acc[0][1] += a0.x * b.y; acc[0][2] += a0.x * b.z; acc[0][3] += a0.x * b.w;
            acc[1][0] += a0.y * b.x; acc[1][1] += a0.y * b.y; acc[1][2] += a0.y * b.z; acc[1][3] += a0.y * b.w;
            acc[2][0] += a0.z * b.x; acc[2][1] += a0.z * b.y; acc[2][2] += a0.z * b.z; acc[2][3] += a0.z * b.w;
            acc[3][0] += a0.w * b.x; acc[3][1] += a0.w * b.y; acc[3][2] += a0.w * b.z; acc[3][3] += a0.w * b.w;
            acc[4][0] += a1.x * b.x; acc[4][1] += a1.x * b.y; acc[4][2] += a1.x * b.z; acc[4][3] += a1.x * b.w;
            acc[5][0] += a1.y * b.x; acc[5][1] += a1.y * b.y; acc[5][2] += a1.y * b.z; acc[5][3] += a1.y * b.w;
            acc[6][0] += a1.z * b.x; acc[6][1] += a1.z * b.y; acc[6][2] += a1.z * b.z; acc[6][3] += a1.z * b.w;
            acc[7][0] += a1.w * b.x; acc[7][1] += a1.w * b.y; acc[7][2] += a1.w * b.z; acc[7][3] += a1.w * b.w;
        }
        if (kt < 15) {
            int nxt = cur ^ 1;
            As[nxt][ak4+0][arow] = na0.x; As[nxt][ak4+1][arow] = na0.y;
            As[nxt][ak4+2][arow] = na0.z; As[nxt][ak4+3][arow] = na0.w;
            As[nxt][ak4+0][arow+64] = na1.x; As[nxt][ak4+1][arow+64] = na1.y;
            As[nxt][ak4+2][arow+64] = na1.z; As[nxt][ak4+3][arow+64] = na1.w;
            *(float4*)&Bs[nxt][bk][bn4] = nb;
        }
        __syncthreads();
        cur ^= 1;
    }
    #pragma unroll
    for (int i = 0; i < 8; ++i) {
        float4 o;
        o.x = acc[i][0]; o.y = acc[i][1]; o.z = acc[i][2]; o.w = acc[i][3];
        *(float4*)(g_M + (size_t)(m0 + ty * 8 + i) * 256 + n0 + tx * 4) = o;
    }
}

// ---------------- fused: bias tile + logits GEMM + exp + split-K softmax -----
// grid (kt=8, qt=8, b=4). Block computes logits for (64 q) x (64 k), reads its
// private 1MB D tile for bias (in smem), and emits per-row partial num/den.
// Parity-swapped phase order: half the blocks stream D while the other half
// runs the FMA-bound GEMM -> in-kernel DRAM/compute overlap.
__global__ __launch_bounds__(256) void fused_att(const float* __restrict__ D,
                                                 float* __restrict__ dummy)
{
    __shared__ __align__(16) float sbias[64][65];
    __shared__ __align__(16) float As[2][16][68];
    __shared__ __align__(16) float Bs[2][16][68];
    __shared__ float ssd[64];

    int t = threadIdx.x;
    int b = blockIdx.z, qt = blockIdx.y, kt = blockIdx.x;
    int q0 = qt * 64, k0 = kt * 64;

    if (t < 64) ssd[t] = g_sd[t];
    __syncthreads();

    int tx = t & 15, ty = t >> 4;
    float acc[4][4] = {};

    auto do_bias = [&]() {
        const float S = g_sc[0], Cc = g_sc[1];
        #pragma unroll 1
        for (int r = 0; r < 16; ++r) {
            int p = (r << 8) + t;
            int qi = p >> 6, kj = p & 63;
            const float4* dp = (const float4*)(
                D + ((size_t)(b * 512 + q0 + qi) * 512 + (k0 + kj)) * 64);
            float sum = 0.f, sq = 0.f, dot = 0.f;
            #pragma unroll
            for (int u = 0; u < 16; ++u) {
                float4 v = dp[u];
                sum += v.x + v.y + v.z + v.w;
                sq  += v.x*v.x + v.y*v.y + v.z*v.z + v.w*v.w;
                dot += v.x*ssd[4*u] + v.y*ssd[4*u+1] + v.z*ssd[4*u+2] + v.w*ssd[4*u+3];
            }
            float mu   = sum * (1.f / 64.f);
            float rinv = rsqrtf(sq * (1.f / 64.f) - mu * mu + LNEPS);
            sbias[qi][kj] = rinv * (dot - mu * S) + Cc;
        }
    };

    auto do_gemm = [&]() {
        int lrow = t >> 2;
        int lk4  = (t & 3) * 4;
        const float* Ap = g_M  + ((size_t)(b * 512 + q0 + lrow)) * 256 + lk4;
        const float* Bp = g_Fn + ((size_t)(b * 512 + k0 + lrow)) * 256 + lk4;
        {
            float4 av = *(const float4*)Ap;
            float4 bv = *(const float4*)Bp;
            As[0][lk4+0][lrow] = av.x; As[0][lk4+1][lrow] = av.y;
            As[0][lk4+2][lrow] = av.z; As[0][lk4+3][lrow] = av.w;
            Bs[0][lk4+0][lrow] = bv.x; Bs[0][lk4+1][lrow] = bv.y;
            Bs[0][lk4+2][lrow] = bv.z; Bs[0][lk4+3][lrow] = bv.w;
        }
        __syncthreads();
        int cur = 0;
        for (int kc = 0; kc < 16; ++kc) {
            float4 na, nb;
            if (kc < 15) {
                na = *(const float4*)(Ap + (kc + 1) * 16);
                nb = *(const float4*)(Bp + (kc + 1) * 16);
            }
            #pragma unroll
            for (int k = 0; k < 16; ++k) {
                float4 a = *(float4*)&As[cur][k][ty * 4];
                float4 v = *(float4*)&Bs[cur][k][tx * 4];
                acc[0][0] += a.x * v.x; acc[0][1] += a.x * v.y; acc[0][2] += a.x * v.z; acc[0][3] += a.x * v.w;
                acc[1][0] += a.y * v.x; acc[1][1] += a.y * v.y; acc[1][2] += a.y * v.z; acc[1][3] += a.y * v.w;
                acc[2][0] += a.z * v.x; acc[2][1] += a.z * v.y; acc[2][2] += a.z * v.z; acc[2][3] += a.z * v.w;
                acc[3][0] += a.w * v.x; acc[3][1] += a.w * v.y; acc[3][2] += a.w * v.z; acc[3][3] += a.w * v.w;
            }
            if (kc < 15) {
                int nxt = cur ^ 1;
                As[nxt][lk4+0][lrow] = na.x; As[nxt][lk4+1][lrow] = na.y;
                As[nxt][lk4+2][lrow] = na.z; As[nxt][lk4+3][lrow] = na.w;
                Bs[nxt][lk4+0][lrow] = nb.x; Bs[nxt][lk4+1][lrow] = nb.y;
                Bs[nxt][lk4+2][lrow] = nb.z; Bs[nxt][lk4+3][lrow] = nb.w;
            }
            __syncthreads();
            cur ^= 1;
        }
    };

    if ((qt ^ kt) & 1) { do_gemm(); do_bias(); }
    else               { do_bias(); do_gemm(); }
    __syncthreads();

    // exp (no-max softmax: logits ~ N(0,1), fp32-safe) + split-K partials
    float4 vsv = *(const float4*)(g_vsum + b * 512 + k0 + tx * 4);
    float vsa[4] = {vsv.x, vsv.y, vsv.z, vsv.w};
    #pragma unroll
    for (int i = 0; i < 4; ++i) {
        int qi = ty * 4 + i;
        float den = 0.f, num = 0.f;
        #pragma unroll
        for (int j = 0; j < 4; ++j) {
            float e = __expf(acc[i][j] + sbias[qi][tx * 4 + j]);
            den += e;
            num += e * vsa[j];
        }
        #pragma unroll
        for (int o = 8; o; o >>= 1) {
            den += __shfl_xor_sync(0xffffffffu, den, o);
            num += __shfl_xor_sync(0xffffffffu, num, o);
        }
        if (tx == 0) {
            int row = b * 512 + q0 + qi;
            g_pden[kt][row] = den;
            g_pnum[kt][row] = num;
        }
    }
    (void)dummy;
}

// ---------------- finalize: out = sum(num)/sum(den) over 8 k-chunks ----------
__global__ __launch_bounds__(256) void finalize_kernel(float* __restrict__ out)
{
    int row = blockIdx.x * 256 + threadIdx.x;   // 0..2047
    float num = 0.f, den = 0.f;
    #pragma unroll
    for (int k = 0; k < 8; ++k) { num += g_pnum[k][row]; den += g_pden[k][row]; }
    out[row] = num / den;
}

// ---------------- launch ------------------------------------------------------
extern "C" void kernel_launch(void* const* d_in, const int* in_sizes, int n_in,
                              void* d_out, int out_size)
{
    (void)in_sizes; (void)n_in; (void)out_size;
    const float* F   = (const float*)d_in[0];
    const float* D   = (const float*)d_in[1];
    const float* Wq  = (const float*)d_in[2];
    const float* Wk  = (const float*)d_in[3];
    const float* Wv  = (const float*)d_in[4];
    const float* gf  = (const float*)d_in[5];
    const float* bf  = (const float*)d_in[6];
    const float* gp  = (const float*)d_in[7];
    const float* bp  = (const float*)d_in[8];
    const float* Wpt = (const float*)d_in[9];
    const float* bpt = (const float*)d_in[10];
    const float* Wph = (const float*)d_in[11];
    float* out = (float*)d_out;

    prep_small<<<1, 64>>>(gp, bp, Wpt, bpt, Wph);
    prep_w2<<<64, 256>>>(Wq, Wk);
    prep_wvsum<<<32, 256>>>(Wv);
    ln_kernel<<<256, 256>>>(F, gf, bf);
    gemm_M<<<dim3(4, 16), 256>>>();
    fused_att<<<dim3(8, 8, 4), 256>>>(D, out);
    finalize_kernel<<<8, 256>>>(out);
}

// round 14
// speedup vs baseline: 1.1279x; 1.1279x over previous
#include <cuda_runtime.h>

#define LNEPS 1e-3f
#define SCALAR 0.0625f   // 1/sqrt(256)

// ---------------- scratch (device globals; no allocations allowed) ----------
__device__ float g_Fn[2048 * 256];        // LayerNorm(F)
__device__ float g_M [2048 * 256];        // Fn @ W2  (W2 = scalar*Wq@Wk^T)
__device__ float g_W2[256 * 256];
__device__ float g_vsum[2048];            // row sums of V
__device__ float g_sd[64];                // scalar * g_p[d] * w_eff[d]
__device__ float g_sc[2];                 // [0]=sum(g_sd), [1]=scalar*const
__device__ float g_wvsum[256];            // Wv @ ones
__device__ float g_pnum[8][2048];         // split-K softmax partials
__device__ float g_pden[8][2048];

// ---------------- prep A: fold pair-path weights (tiny) ----------------------
__global__ __launch_bounds__(64) void prep_small(
    const float* __restrict__ gp, const float* __restrict__ bp,
    const float* __restrict__ Wpt, const float* __restrict__ bpt,
    const float* __restrict__ Wph)
{
    __shared__ float weff[64];
    int t = threadIdx.x;
    float acc = 0.f;
    #pragma unroll 8
    for (int p = 0; p < 128; ++p) acc += Wpt[t * 128 + p] * Wph[p];
    weff[t] = acc;
    g_sd[t] = SCALAR * gp[t] * acc;
    __syncthreads();
    float v1 = SCALAR * gp[t] * weff[t];
    float v2 = bp[t] * weff[t];
    float v3 = bpt[t] * Wph[t] + bpt[t + 64] * Wph[t + 64];
    #pragma unroll
    for (int o = 16; o; o >>= 1) {
        v1 += __shfl_xor_sync(0xffffffffu, v1, o);
        v2 += __shfl_xor_sync(0xffffffffu, v2, o);
        v3 += __shfl_xor_sync(0xffffffffu, v3, o);
    }
    __shared__ float red[3][2];
    if ((t & 31) == 0) { red[0][t >> 5] = v1; red[1][t >> 5] = v2; red[2][t >> 5] = v3; }
    __syncthreads();
    if (t == 0) {
        g_sc[0] = red[0][0] + red[0][1];
        g_sc[1] = SCALAR * (red[1][0] + red[1][1] + red[2][0] + red[2][1]);
    }
}

// ---------------- prep B: W2 = SCALAR * Wq @ Wk^T (256x256, NT) --------------
__global__ __launch_bounds__(256) void prep_w2(
    const float* __restrict__ Wq, const float* __restrict__ Wk)
{
    __shared__ __align__(16) float As[32][36], Bs[32][36];
    int t = threadIdx.x;
    int m0 = (blockIdx.x >> 3) * 32, n0 = (blockIdx.x & 7) * 32;
    int lr = t >> 3, lc4 = (t & 7) * 4;
    int ty = t >> 4, tx = t & 15;
    float acc[2][2] = {};
    for (int kc = 0; kc < 256; kc += 32) {
        *(float4*)&As[lr][lc4] = *(const float4*)(Wq + (size_t)(m0 + lr) * 256 + kc + lc4);
        *(float4*)&Bs[lr][lc4] = *(const float4*)(Wk + (size_t)(n0 + lr) * 256 + kc + lc4);
        __syncthreads();
        #pragma unroll
        for (int k = 0; k < 32; ++k) {
            float a0 = As[ty * 2][k], a1 = As[ty * 2 + 1][k];
            float b0 = Bs[tx * 2][k], b1 = Bs[tx * 2 + 1][k];
            acc[0][0] += a0 * b0; acc[0][1] += a0 * b1;
            acc[1][0] += a1 * b0; acc[1][1] += a1 * b1;
        }
        __syncthreads();
    }
    #pragma unroll
    for (int i = 0; i < 2; ++i)
        #pragma unroll
        for (int j = 0; j < 2; ++j)
            g_W2[(m0 + ty * 2 + i) * 256 + n0 + tx * 2 + j] = SCALAR * acc[i][j];
}

// ---------------- prep C: wvsum[f] = sum_a Wv[f,a] ---------------------------
__global__ __launch_bounds__(256) void prep_wvsum(const float* __restrict__ Wv)
{
    int warp = threadIdx.x >> 5, lane = threadIdx.x & 31;
    int f = blockIdx.x * 8 + warp;
    const float* row = Wv + (size_t)f * 256;
    float acc = 0.f;
    #pragma unroll
    for (int i = 0; i < 8; ++i) acc += row[lane + 32 * i];
    #pragma unroll
    for (int o = 16; o; o >>= 1) acc += __shfl_xor_sync(0xffffffffu, acc, o);
    if (lane == 0) g_wvsum[f] = acc;
}

// ---------------- LayerNorm(F) + vsum ----------------------------------------
__global__ __launch_bounds__(256) void ln_kernel(
    const float* __restrict__ F, const float* __restrict__ gf,
    const float* __restrict__ bf)
{
    int row  = blockIdx.x * 8 + (threadIdx.x >> 5);
    int lane = threadIdx.x & 31;
    const float* x = F + (size_t)row * 256;
    float4 a = *(const float4*)(x + lane * 4);
    float4 b = *(const float4*)(x + 128 + lane * 4);
    float s = a.x + a.y + a.z + a.w + b.x + b.y + b.z + b.w;
    float q = a.x*a.x + a.y*a.y + a.z*a.z + a.w*a.w
            + b.x*b.x + b.y*b.y + b.z*b.z + b.w*b.w;
    #pragma unroll
    for (int o = 16; o; o >>= 1) {
        s += __shfl_xor_sync(0xffffffffu, s, o);
        q += __shfl_xor_sync(0xffffffffu, q, o);
    }
    float mu   = s * (1.f / 256.f);
    float rinv = rsqrtf(q * (1.f / 256.f) - mu * mu + LNEPS);

    float4 g0 = *(const float4*)(gf + lane * 4);
    float4 b0 = *(const float4*)(bf + lane * 4);
    float4 g1 = *(const float4*)(gf + 128 + lane * 4);
    float4 b1 = *(const float4*)(bf + 128 + lane * 4);
    float4 f0, f1;
    f0.x = (a.x - mu) * rinv * g0.x + b0.x;
    f0.y = (a.y - mu) * rinv * g0.y + b0.y;
    f0.z = (a.z - mu) * rinv * g0.z + b0.z;
    f0.w = (a.w - mu) * rinv * g0.w + b0.w;
    f1.x = (b.x - mu) * rinv * g1.x + b1.x;
    f1.y = (b.y - mu) * rinv * g1.y + b1.y;
    f1.z = (b.z - mu) * rinv * g1.z + b1.z;
    f1.w = (b.w - mu) * rinv * g1.w + b1.w;

    *(float4*)(g_Fn + (size_t)row * 256 + lane * 4)       = f0;
    *(float4*)(g_Fn + (size_t)row * 256 + 128 + lane * 4) = f1;

    float4 w0 = *(const float4*)(g_wvsum + lane * 4);
    float4 w1 = *(const float4*)(g_wvsum + 128 + lane * 4);
    float p = f0.x*w0.x + f0.y*w0.y + f0.z*w0.z + f0.w*w0.w
            + f1.x*w1.x + f1.y*w1.y + f1.z*w1.z + f1.w*w1.w;
    #pragma unroll
    for (int o = 16; o; o >>= 1) p += __shfl_xor_sync(0xffffffffu, p, o);
    if (lane == 0) g_vsum[row] = p;
}

// ---------------- GEMM: M = Fn @ W2  (NN, 128x64 tile, double-buffered) ------
__global__ __launch_bounds__(256) void gemm_M()
{
    __shared__ __align__(16) float As[2][16][132];
    __shared__ __align__(16) float Bs[2][16][68];
    int t  = threadIdx.x;
    int tx = t & 15, ty = t >> 4;
    int m0 = blockIdx.y * 128, n0 = blockIdx.x * 64;

    int arow = t >> 2;
    int ak4  = (t & 3) * 4;
    int bk   = t >> 4;
    int bn4  = (t & 15) * 4;

    const float* Aptr0 = g_Fn + (size_t)(m0 + arow) * 256 + ak4;
    const float* Aptr1 = Aptr0 + 64 * 256;
    const float* Bptr  = g_W2 + (size_t)bk * 256 + n0 + bn4;

    float acc[8][4] = {};
    {
        float4 a0 = *(const float4*)(Aptr0);
        float4 a1 = *(const float4*)(Aptr1);
        float4 bv = *(const float4*)(Bptr);
        As[0][ak4+0][arow] = a0.x; As[0][ak4+1][arow] = a0.y;
        As[0][ak4+2][arow] = a0.z; As[0][ak4+3][arow] = a0.w;
        As[0][ak4+0][arow+64] = a1.x; As[0][ak4+1][arow+64] = a1.y;
        As[0][ak4+2][arow+64] = a1.z; As[0][ak4+3][arow+64] = a1.w;
        *(float4*)&Bs[0][bk][bn4] = bv;
    }
    __syncthreads();
    int cur = 0;
    for (int kt = 0; kt < 16; ++kt) {
        float4 na0, na1, nb;
        if (kt < 15) {
            na0 = *(const float4*)(Aptr0 + (kt + 1) * 16);
            na1 = *(const float4*)(Aptr1 + (kt + 1) * 16);
            nb  = *(const float4*)(Bptr + (size_t)(kt + 1) * 16 * 256);
        }
        #pragma unroll
        for (int k = 0; k < 16; ++k) {
            float4 a0 = *(float4*)&As[cur][k][ty * 8];
            float4 a1 = *(float4*)&As[cur][k][ty * 8 + 4];
            float4 b  = *(float4*)&Bs[cur][k][tx * 4];
            acc[0][0] += a0.x * b.x; acc[0][1] += a0.x * b.y; acc[0][2] += a0.x * b.z; acc[0][3] += a0.x * b.w;
            acc[1][0] += a0.y * b.x; acc[1][1] += a0.y * b.y; acc[1][2] += a0.y * b.z; acc[1][3] += a0.y * b.w;
            acc[2][0] += a0.z * b.x; acc[2][1] += a0.z * b.y; acc[2][2] += a0.z * b.z; acc[2][3] += a0.z * b.w;
            acc[3][0] += a0.w * b.x; acc[3][1] += a0.w * b.y; acc[3][2] += a0.w * b.z; acc[3][3] += a0.w * b.w;
            acc[4][0] += a1.x * b.x; acc[4][1] += a1.x * b.y; acc[4][2] += a1.x * b.z; acc[4][3] += a1.x * b.w;
            acc[5][0] += a1.y * b.x; acc[5][1] += a1.y * b.y; acc[5][2] += a1.y * b.z; acc[5][3] += a1.y * b.w;
            acc[6][0] += a1.z * b.x; acc[6][1] += a1.z * b.y; acc[6][2] += a1.z * b.z; acc[6][3] += a1.z * b.w;
            acc[7][0] += a1.w * b.x; acc[7][1] += a1.w * b.y; acc[7][2] += a1.w * b.z; acc[7][3] += a1.w * b.w;
        }
        if (kt < 15) {
            int nxt = cur ^ 1;
            As[nxt][ak4+0][arow] = na0.x; As[nxt][ak4+1][arow] = na0.y;
            As[nxt][ak4+2][arow] = na0.z; As[nxt][ak4+3][arow] = na0.w;
            As[nxt][ak4+0][arow+64] = na1.x; As[nxt][ak4+1][arow+64] = na1.y;
            As[nxt][ak4+2][arow+64] = na1.z; As[nxt][ak4+3][arow+64] = na1.w;
            *(float4*)&Bs[nxt][bk][bn4] = nb;
        }
        __syncthreads();
        cur ^= 1;
    }
    #pragma unroll
    for (int i = 0; i < 8; ++i) {
        float4 o;
        o.x = acc[i][0]; o.y = acc[i][1]; o.z = acc[i][2]; o.w = acc[i][3];
        *(float4*)(g_M + (size_t)(m0 + ty * 8 + i) * 256 + n0 + tx * 4) = o;
    }
}

// ---------------- fused: bias tile + logits GEMM + exp + split-K softmax -----
// grid (kt=8, qt=8, b=4). Block handles (64 q) x (64 k). Bias phase streams
// the block's private 1MB D tile with COALESCED loads: 8 lanes per 64-float
// row (each LDG.128 covers 4 rows x 128B = 4 fully-used cache lines), 2 rows
// per thread, unroll 2 -> MLP=8. Parity-swapped phase order keeps half the
// blocks in the FMA-bound GEMM while the other half streams DRAM.
__global__ __launch_bounds__(256) void fused_att(const float* __restrict__ D,
                                                 float* __restrict__ dummy)
{
    __shared__ __align__(16) float sbias[64][65];
    __shared__ __align__(16) float As[2][16][68];
    __shared__ __align__(16) float Bs[2][16][68];
    __shared__ __align__(16) float ssd[64];

    int t = threadIdx.x;
    int b = blockIdx.z, qt = blockIdx.y, kt = blockIdx.x;
    int q0 = qt * 64, k0 = kt * 64;

    if (t < 64) ssd[t] = g_sd[t];
    __syncthreads();

    int tx = t & 15, ty = t >> 4;
    float acc[4][4] = {};

    auto do_bias = [&]() {
        const float S = g_sc[0], Cc = g_sc[1];
        int warp = t >> 5, lane = t & 31;
        int sub = lane >> 3;      // 0..3
        int c   = lane & 7;       // 0..7
        float4 s0 = *(const float4*)(ssd + c * 4);
        float4 s1 = *(const float4*)(ssd + 32 + c * 4);
        const float* Dbase = D + ((size_t)(b * 512 + q0) * 512 + k0) * 64;
        // tile rows idx = qi*64+kj; address = Dbase + (qi*512 + kj)*64
        #pragma unroll 2
        for (int it = 0; it < 64; ++it) {
            int idx0 = it * 64 + warp * 8 + sub;     // rows idx0 and idx0+4 share qi
            int qi = idx0 >> 6;
            int kj0 = idx0 & 63;
            const float* p0 = Dbase + ((size_t)qi * 512 + kj0) * 64;
            const float* p1 = p0 + 4 * 64;           // kj0+4 (same qi)
            float4 a0 = *(const float4*)(p0 + c * 4);
            float4 b0 = *(const float4*)(p0 + 32 + c * 4);
            float4 a1 = *(const float4*)(p1 + c * 4);
            float4 b1 = *(const float4*)(p1 + 32 + c * 4);

            float sum0 = a0.x + a0.y + a0.z + a0.w + b0.x + b0.y + b0.z + b0.w;
            float sq0  = a0.x*a0.x + a0.y*a0.y + a0.z*a0.z + a0.w*a0.w
                       + b0.x*b0.x + b0.y*b0.y + b0.z*b0.z + b0.w*b0.w;
            float dp0  = a0.x*s0.x + a0.y*s0.y + a0.z*s0.z + a0.w*s0.w
                       + b0.x*s1.x + b0.y*s1.y + b0.z*s1.z + b0.w*s1.w;
            float sum1 = a1.x + a1.y + a1.z + a1.w + b1.x + b1.y + b1.z + b1.w;
            float sq1  = a1.x*a1.x + a1.y*a1.y + a1.z*a1.z + a1.w*a1.w
                       + b1.x*b1.x + b1.y*b1.y + b1.z*b1.z + b1.w*b1.w;
            float dp1  = a1.x*s0.x + a1.y*s0.y + a1.z*s0.z + a1.w*s0.w
                       + b1.x*s1.x + b1.y*s1.y + b1.z*s1.z + b1.w*s1.w;

            #pragma unroll
            for (int o = 4; o; o >>= 1) {
                sum0 += __shfl_xor_sync(0xffffffffu, sum0, o);
                sq0  += __shfl_xor_sync(0xffffffffu, sq0,  o);
                dp0  += __shfl_xor_sync(0xffffffffu, dp0,  o);
                sum1 += __shfl_xor_sync(0xffffffffu, sum1, o);
                sq1  += __shfl_xor_sync(0xffffffffu, sq1,  o);
                dp1  += __shfl_xor_sync(0xffffffffu, dp1,  o);
            }
            if (c == 0) {
                float mu0   = sum0 * (1.f / 64.f);
                float rinv0 = rsqrtf(sq0 * (1.f / 64.f) - mu0 * mu0 + LNEPS);
                sbias[qi][kj0] = rinv0 * (dp0 - mu0 * S) + Cc;
                float mu1   = sum1 * (1.f / 64.f);
                float rinv1 = rsqrtf(sq1 * (1.f / 64.f) - mu1 * mu1 + LNEPS);
                sbias[qi][kj0 + 4] = rinv1 * (dp1 - mu1 * S) + Cc;
            }
        }
    };

    auto do_gemm = [&]() {
        int lrow = t >> 2;
        int lk4  = (t & 3) * 4;
        const float* Ap = g_M  + ((size_t)(b * 512 + q0 + lrow)) * 256 + lk4;
        const float* Bp = g_Fn + ((size_t)(b * 512 + k0 + lrow)) * 256 + lk4;
        {
            float4 av = *(const float4*)Ap;
            float4 bv = *(const float4*)Bp;
            As[0][lk4+0][lrow] = av.x; As[0][lk4+1][lrow] = av.y;
            As[0][lk4+2][lrow] = av.z; As[0][lk4+3][lrow] = av.w;
            Bs[0][lk4+0][lrow] = bv.x; Bs[0][lk4+1][lrow] = bv.y;
            Bs[0][lk4+2][lrow] = bv.z; Bs[0][lk4+3][lrow] = bv.w;
        }
        __syncthreads();
        int cur = 0;
        for (int kc = 0; kc < 16; ++kc) {
            float4 na, nb;
            if (kc < 15) {
                na = *(const float4*)(Ap + (kc + 1) * 16);
                nb = *(const float4*)(Bp + (kc + 1) * 16);
            }
            #pragma unroll
            for (int k = 0; k < 16; ++k) {
                float4 a = *(float4*)&As[cur][k][ty * 4];
                float4 v = *(float4*)&Bs[cur][k][tx * 4];
                acc[0][0] += a.x * v.x; acc[0][1] += a.x * v.y; acc[0][2] += a.x * v.z; acc[0][3] += a.x * v.w;
                acc[1][0] += a.y * v.x; acc[1][1] += a.y * v.y; acc[1][2] += a.y * v.z; acc[1][3] += a.y * v.w;
                acc[2][0] += a.z * v.x; acc[2][1] += a.z * v.y; acc[2][2] += a.z * v.z; acc[2][3] += a.z * v.w;
                acc[3][0] += a.w * v.x; acc[3][1] += a.w * v.y; acc[3][2] += a.w * v.z; acc[3][3] += a.w * v.w;
            }
            if (kc < 15) {
                int nxt = cur ^ 1;
                As[nxt][lk4+0][lrow] = na.x; As[nxt][lk4+1][lrow] = na.y;
                As[nxt][lk4+2][lrow] = na.z; As[nxt][lk4+3][lrow] = na.w;
                Bs[nxt][lk4+0][lrow] = nb.x; Bs[nxt][lk4+1][lrow] = nb.y;
                Bs[nxt][lk4+2][lrow] = nb.z; Bs[nxt][lk4+3][lrow] = nb.w;
            }
            __syncthreads();
            cur ^= 1;
        }
    };

    if ((qt ^ kt) & 1) { do_gemm(); do_bias(); }
    else               { do_bias(); do_gemm(); }
    __syncthreads();

    // exp (no-max softmax: logits ~ N(0,1), fp32-safe) + split-K partials
    float4 vsv = *(const float4*)(g_vsum + b * 512 + k0 + tx * 4);
    float vsa[4] = {vsv.x, vsv.y, vsv.z, vsv.w};
    #pragma unroll
    for (int i = 0; i < 4; ++i) {
        int qi = ty * 4 + i;
        float den = 0.f, num = 0.f;
        #pragma unroll
        for (int j = 0; j < 4; ++j) {
            float e = __expf(acc[i][j] + sbias[qi][tx * 4 + j]);
            den += e;
            num += e * vsa[j];
        }
        #pragma unroll
        for (int o = 8; o; o >>= 1) {
            den += __shfl_xor_sync(0xffffffffu, den, o);
            num += __shfl_xor_sync(0xffffffffu, num, o);
        }
        if (tx == 0) {
            int row = b * 512 + q0 + qi;
            g_pden[kt][row] = den;
            g_pnum[kt][row] = num;
        }
    }
    (void)dummy;
}

// ---------------- finalize: out = sum(num)/sum(den) over 8 k-chunks ----------
__global__ __launch_bounds__(256) void finalize_kernel(float* __restrict__ out)
{
    int row = blockIdx.x * 256 + threadIdx.x;   // 0..2047
    float num = 0.f, den = 0.f;
    #pragma unroll
    for (int k = 0; k < 8; ++k) { num += g_pnum[k][row]; den += g_pden[k][row]; }
    out[row] = num / den;
}

// ---------------- launch ------------------------------------------------------
extern "C" void kernel_launch(void* const* d_in, const int* in_sizes, int n_in,
                              void* d_out, int out_size)
{
    (void)in_sizes; (void)n_in; (void)out_size;
    const float* F   = (const float*)d_in[0];
    const float* D   = (const float*)d_in[1];
    const float* Wq  = (const float*)d_in[2];
    const float* Wk  = (const float*)d_in[3];
    const float* Wv  = (const float*)d_in[4];
    const float* gf  = (const float*)d_in[5];
    const float* bf  = (const float*)d_in[6];
    const float* gp  = (const float*)d_in[7];
    const float* bp  = (const float*)d_in[8];
    const float* Wpt = (const float*)d_in[9];
    const float* bpt = (const float*)d_in[10];
    const float* Wph = (const float*)d_in[11];
    float* out = (float*)d_out;

    prep_small<<<1, 64>>>(gp, bp, Wpt, bpt, Wph);
    prep_w2<<<64, 256>>>(Wq, Wk);
    prep_wvsum<<<32, 256>>>(Wv);
    ln_kernel<<<256, 256>>>(F, gf, bf);
    gemm_M<<<dim3(4, 16), 256>>>();
    fused_att<<<dim3(8, 8, 4), 256>>>(D, out);
    finalize_kernel<<<8, 256>>>(out);
}